// round 3
// baseline (speedup 1.0000x reference)
#include <cuda_runtime.h>
#include <math.h>

#define D3 (128 * 128 * 128)
#define NSTEPS 111
#define DT 0.03125f

// 64MB scratch: volume re-laid-out as [B, z, y, x] float4 (channels interleaved)
__device__ float4 g_vol[2 * D3];

// ---------------------------------------------------------------------------
// Kernel 1: transpose [B,4,D,D,D] -> [B,D,D,D,4] (float4 per voxel)
// ---------------------------------------------------------------------------
__global__ void transpose_vol_kernel(const float* __restrict__ vol, int total) {
    int idx = blockIdx.x * blockDim.x + threadIdx.x;   // over B*D3
    if (idx >= total) return;
    int b = idx / D3;
    int s = idx - b * D3;
    const float* p = vol + (size_t)b * 4 * D3 + s;
    float4 v;
    v.x = __ldg(p);
    v.y = __ldg(p + D3);
    v.z = __ldg(p + 2 * D3);
    v.w = __ldg(p + 3 * D3);
    g_vol[idx] = v;
}

// ---------------------------------------------------------------------------
// Kernel 2: raymarch
// ---------------------------------------------------------------------------
__device__ __forceinline__ float4 lerp4(float4 a, float4 b, float f) {
    float g = 1.0f - f;
    float4 r;
    r.x = a.x * g + b.x * f;
    r.y = a.y * g + b.y * f;
    r.z = a.z * g + b.z * f;
    r.w = a.w * g + b.w * f;
    return r;
}

__global__ __launch_bounds__(256) void raymarch_kernel(
    const float* __restrict__ camrot,     // [B,3,3]
    const float* __restrict__ campos,     // [B,3]
    const float* __restrict__ focal,      // [B,2]
    const float* __restrict__ princpt,    // [B,2]
    const float* __restrict__ pixelcoords,// [B,H,W,2]
    float* __restrict__ out,              // [B,4,H,W]
    int H, int W)
{
    const int w = blockIdx.x * blockDim.x + threadIdx.x;
    const int h = blockIdx.y * blockDim.y + threadIdx.y;
    const int b = blockIdx.z;
    if (w >= W || h >= H) return;

    // ---- ray setup (bit-exact vs JAX: correctly-rounded ops, no FMA) ----
    const float px = pixelcoords[(((size_t)b * H + h) * W + w) * 2 + 0];
    const float py = pixelcoords[(((size_t)b * H + h) * W + w) * 2 + 1];
    const float vx = __fdiv_rn(__fsub_rn(px, princpt[b * 2 + 0]), focal[b * 2 + 0]);
    const float vy = __fdiv_rn(__fsub_rn(py, princpt[b * 2 + 1]), focal[b * 2 + 1]);
    const float vz = 1.0f;

    // out_j = sum_i R[i][j] * v_i   (einsum 'bij,bhwi->bhwj'), sequential adds
    const float* R = camrot + b * 9;
    float dx = __fadd_rn(__fadd_rn(__fmul_rn(R[0], vx), __fmul_rn(R[3], vy)), __fmul_rn(R[6], vz));
    float dy = __fadd_rn(__fadd_rn(__fmul_rn(R[1], vx), __fmul_rn(R[4], vy)), __fmul_rn(R[7], vz));
    float dz = __fadd_rn(__fadd_rn(__fmul_rn(R[2], vx), __fmul_rn(R[5], vy)), __fmul_rn(R[8], vz));

    // raydir / sqrt(sum(raydir**2)): division (not reciprocal-mult), IEEE sqrt
    const float ss = __fadd_rn(__fadd_rn(__fmul_rn(dx, dx), __fmul_rn(dy, dy)),
                               __fmul_rn(dz, dz));
    const float nrm = __fsqrt_rn(ss);
    dx = __fdiv_rn(dx, nrm);
    dy = __fdiv_rn(dy, nrm);
    dz = __fdiv_rn(dz, nrm);

    const float cx = campos[b * 3 + 0];
    const float cy = campos[b * 3 + 1];
    const float cz = campos[b * 3 + 2];

    // ---- ray-AABB [-1,1]^3, correctly-rounded ----
    const float t1x = __fdiv_rn(__fsub_rn(-1.0f, cx), dx);
    const float t2x = __fdiv_rn(__fsub_rn( 1.0f, cx), dx);
    const float t1y = __fdiv_rn(__fsub_rn(-1.0f, cy), dy);
    const float t2y = __fdiv_rn(__fsub_rn( 1.0f, cy), dy);
    const float t1z = __fdiv_rn(__fsub_rn(-1.0f, cz), dz);
    const float t2z = __fdiv_rn(__fsub_rn( 1.0f, cz), dz);
    const float tmin = fmaxf(fminf(t1x, t2x),
                      fmaxf(fminf(t1y, t2y), fminf(t1z, t2z)));
    const float tmax = fminf(fmaxf(t1x, t2x),
                      fminf(fmaxf(t1y, t2y), fmaxf(t1z, t2z)));
    const bool hit = tmin < tmax;
    const float t0 = fmaxf(hit ? tmin : 0.0f, 0.0f);

    // raypos = campos + raydir * t0   (mul then add, no FMA)
    float posx = __fadd_rn(cx, __fmul_rn(dx, t0));
    float posy = __fadd_rn(cy, __fmul_rn(dy, t0));
    float posz = __fadd_rn(cz, __fmul_rn(dz, t0));
    // DT = 2^-5: these multiplies are exact, matching raydir * DT elementwise
    const float sx = __fmul_rn(dx, DT);
    const float sy = __fmul_rn(dy, DT);
    const float sz = __fmul_rn(dz, DT);

    float accr = 0.0f, accg = 0.0f, accb = 0.0f, acca = 0.0f;

    if (hit) {
        const float4* __restrict__ vol = g_vol + (size_t)b * D3;
        bool entered = false;
        #pragma unroll 1
        for (int s = 0; s < NSTEPS; s++) {
            const bool valid =
                (posx > -1.0f) & (posx < 1.0f) &
                (posy > -1.0f) & (posy < 1.0f) &
                (posz > -1.0f) & (posz < 1.0f);
            if (valid) {
                entered = true;
                // g = clip(((pos+1)*0.5)*(n-1), 0, n-1), matching op order
                float gx = fminf(fmaxf(__fmul_rn(__fmul_rn(__fadd_rn(posx, 1.0f), 0.5f), 127.0f), 0.0f), 127.0f);
                float gy = fminf(fmaxf(__fmul_rn(__fmul_rn(__fadd_rn(posy, 1.0f), 0.5f), 127.0f), 0.0f), 127.0f);
                float gz = fminf(fmaxf(__fmul_rn(__fmul_rn(__fadd_rn(posz, 1.0f), 0.5f), 127.0f), 0.0f), 127.0f);
                int ix = min((int)gx, 126);
                int iy = min((int)gy, 126);
                int iz = min((int)gz, 126);
                float fx = __fsub_rn(gx, (float)ix);
                float fy = __fsub_rn(gy, (float)iy);
                float fz = __fsub_rn(gz, (float)iz);

                const int o = (iz * 128 + iy) * 128 + ix;
                float4 v000 = __ldg(vol + o);
                float4 v001 = __ldg(vol + o + 1);
                float4 v010 = __ldg(vol + o + 128);
                float4 v011 = __ldg(vol + o + 129);
                float4 v100 = __ldg(vol + o + 16384);
                float4 v101 = __ldg(vol + o + 16385);
                float4 v110 = __ldg(vol + o + 16512);
                float4 v111 = __ldg(vol + o + 16513);

                float4 c00 = lerp4(v000, v001, fx);
                float4 c01 = lerp4(v010, v011, fx);
                float4 c10 = lerp4(v100, v101, fx);
                float4 c11 = lerp4(v110, v111, fx);
                float4 c0  = lerp4(c00, c01, fy);
                float4 c1  = lerp4(c10, c11, fy);
                float4 samp = lerp4(c0, c1, fz);

                const float contrib =
                    __fsub_rn(fminf(__fadd_rn(acca, __fmul_rn(samp.w, DT)), 1.0f), acca);
                accr = __fadd_rn(accr, __fmul_rn(samp.x, contrib));
                accg = __fadd_rn(accg, __fmul_rn(samp.y, contrib));
                accb = __fadd_rn(accb, __fmul_rn(samp.z, contrib));
                acca = __fadd_rn(acca, contrib);
                if (acca >= 1.0f) break;   // saturated: contrib == 0 forever
            } else if (entered) {
                break;                      // convex box: exited for good
            }
            // raypos = raypos + raydir*DT (step product exact, add rn)
            posx = __fadd_rn(posx, sx);
            posy = __fadd_rn(posy, sy);
            posz = __fadd_rn(posz, sz);
        }
    }

    const size_t plane = (size_t)H * W;
    const size_t pix = (size_t)h * W + w;
    float* ob = out + (size_t)b * 4 * plane;
    ob[0 * plane + pix] = accr;
    ob[1 * plane + pix] = accg;
    ob[2 * plane + pix] = accb;
    ob[3 * plane + pix] = acca;
}

// ---------------------------------------------------------------------------
// Launch
// ---------------------------------------------------------------------------
extern "C" void kernel_launch(void* const* d_in, const int* in_sizes, int n_in,
                              void* d_out, int out_size) {
    const float* camrot      = (const float*)d_in[0];
    const float* campos      = (const float*)d_in[1];
    const float* focal       = (const float*)d_in[2];
    const float* princpt     = (const float*)d_in[3];
    const float* pixelcoords = (const float*)d_in[4];
    const float* volume      = (const float*)d_in[5];
    float* out = (float*)d_out;

    const int B = in_sizes[1] / 3;                 // campos: [B,3]
    const int HW = in_sizes[4] / (B * 2);          // pixelcoords: [B,H,W,2]
    int H = 256, W = 256;
    if (HW != H * W) {                              // fallback: square image
        int s = (int)(sqrtf((float)HW) + 0.5f);
        H = s; W = s;
    }

    // 1) transpose volume to interleaved float4
    {
        int total = B * D3;
        int threads = 256;
        int blocks = (total + threads - 1) / threads;
        transpose_vol_kernel<<<blocks, threads>>>(volume, total);
    }

    // 2) raymarch
    {
        dim3 block(16, 16);
        dim3 grid((W + 15) / 16, (H + 15) / 16, B);
        raymarch_kernel<<<grid, block>>>(camrot, campos, focal, princpt,
                                         pixelcoords, out, H, W);
    }
}